// round 13
// baseline (speedup 1.0000x reference)
#include <cuda_runtime.h>
#include <cstdint>

#define LRELU_ALPHA 0.2f

typedef unsigned long long u64;

// packed f32x2 helpers (sm_103a FFMA2 is PTX-only)
__device__ __forceinline__ void ffma2(u64 &d, u64 a, u64 b){
    asm("fma.rn.f32x2 %0, %1, %2, %0;" : "+l"(d) : "l"(a), "l"(b));
}
__device__ __forceinline__ u64 pack2(float s){
    u64 d; asm("mov.b64 %0, {%1, %1};" : "=l"(d) : "f"(s)); return d;
}
__device__ __forceinline__ void unpack2(float &lo, float &hi, u64 v){
    asm("mov.b64 {%0,%1}, %2;" : "=f"(lo), "=f"(hi) : "l"(v));
}
__device__ __forceinline__ float hsum2(u64 v){
    float lo, hi;
    asm("mov.b64 {%0,%1}, %2;" : "=f"(lo), "=f"(hi) : "l"(v));
    return lo + hi;
}

// ping-pong activation buffers + transposed weights (allocation-free scratch)
__device__ __align__(16) float g_bufA[67108864];   // h1, h3, d1, d3
__device__ __align__(16) float g_bufB[33554432];   // h2, q,  d2
__device__ __align__(16) float g_wT[55296];        // e2,e3 ci-pair weights

// ---------------------------------------------------------------------------
// Weight transpose: HWIO [tap][ci][co] -> [tap][cipair][co][2]; e2,e3 only.
// dst[((tap*CI/2 + cp)*CO + co)*2 + par] = src[(tap*CI + 2cp+par)*CO + co]
// ---------------------------------------------------------------------------
__global__ void transposeP_kernel(
    const float* __restrict__ e2, const float* __restrict__ e3,
    float* __restrict__ wT)
{
    int seg = blockIdx.y;
    const float* src; int CI, CO, off;
    if (seg == 0){ src=e2; CI=32; CO=64; off=0;     }
    else         { src=e3; CI=64; CO=64; off=18432; }
    int total = 9*CI*CO;
    int i = blockIdx.x*256 + threadIdx.x;
    if (i >= total) return;
    int par = i & 1; int t2 = i >> 1;
    int co = t2 % CO; int t3 = t2 / CO;
    int cih = CI >> 1;
    int cp = t3 % cih; int tap = t3 / cih;
    wT[off + i] = src[(size_t)(tap*CI + 2*cp + par)*CO + co];
}

// ---------------------------------------------------------------------------
// convP2: ci-paired stride-2 SAME conv (pad_lo=0, pad_hi=1), NHWC.
// f32x2 lanes = (even ci, odd ci) partial sums -> x loads are raw LDG.128
// reinterprets (zero pack MOVs). Weights pre-transposed [tap][cipair][co][2].
// ofs[r]/v[r] hoisted per (ky,kx) -- fixes R11 convP's ALU blowup.
// Thread = 2 couts x RP cols. CQ=32 -> warp-uniform x addresses (broadcast).
// ---------------------------------------------------------------------------
template<int CI, int CO, int RP>
__global__ __launch_bounds__(128,3) void convP2_kernel(
    const float* __restrict__ in, const float* __restrict__ wT,
    const float* __restrict__ bias, float* __restrict__ out,
    int N, int Hin, int Win, int Hout, int Wout)
{
    constexpr int CQ  = CO / 2;
    constexpr int G   = 128 / CQ;
    constexpr int CIH = CI / 2;

    const int cq = threadIdx.x % CQ;
    const int g  = threadIdx.x / CQ;
    const int w0 = (blockIdx.x * G + g) * RP;
    const int h  = blockIdx.y;
    const int n  = blockIdx.z;

    u64 acc[RP][2];
    #pragma unroll
    for (int r=0;r<RP;r++){ acc[r][0]=0ull; acc[r][1]=0ull; }

    const float* __restrict__ wb = wT + 4*cq;   // co offset: 2cq couts -> 4cq floats

    #pragma unroll
    for (int ky=0; ky<3; ky++){
        int ihy = h*2 + ky;
        if (ihy >= Hin) continue;
        const float* __restrict__ rowp = in + (size_t)(n*Hin + ihy) * Win * CI;

        #pragma unroll
        for (int kx=0; kx<3; kx++){
            const float* __restrict__ wp = wb + (size_t)((ky*3+kx)*CIH)*CO*2;
            // hoisted per-column offsets (the R11 fix)
            int  ofs[RP];
            bool v[RP];
            #pragma unroll
            for (int r=0;r<RP;r++){
                int iw = (w0+r)*2 + kx;
                v[r]   = (iw < Win);
                ofs[r] = v[r] ? iw*CI : 0;
            }

            #pragma unroll 2
            for (int ci=0; ci<CI; ci+=4){
                const int cp = ci >> 1;
                ulonglong2 wv0 = *reinterpret_cast<const ulonglong2*>(wp + (size_t)cp*CO*2);
                ulonglong2 wv1 = *reinterpret_cast<const ulonglong2*>(wp + (size_t)(cp+1)*CO*2);
                #pragma unroll
                for (int r=0;r<RP;r++){
                    if (v[r]){
                        ulonglong2 xv = *reinterpret_cast<const ulonglong2*>(rowp + ofs[r] + ci);
                        ffma2(acc[r][0], wv0.x, xv.x);
                        ffma2(acc[r][1], wv0.y, xv.x);
                        ffma2(acc[r][0], wv1.x, xv.y);
                        ffma2(acc[r][1], wv1.y, xv.y);
                    }
                }
            }
        }
    }

    const float2 bv = *reinterpret_cast<const float2*>(bias + 2*cq);
    const size_t ob = ((size_t)(n*Hout + h)*Wout + w0)*CO + 2*cq;
    #pragma unroll
    for (int r=0;r<RP;r++){
        float a0 = hsum2(acc[r][0]) + bv.x;
        float a1 = hsum2(acc[r][1]) + bv.y;
        a0 = (a0 > 0.f) ? a0 : LRELU_ALPHA * a0;
        a1 = (a1 > 0.f) ? a1 : LRELU_ALPHA * a1;
        float2 o; o.x = a0; o.y = a1;
        *reinterpret_cast<float2*>(out + ob + (size_t)r*CO) = o;
    }
}

// ---------------------------------------------------------------------------
// R9 wide row-paired deconv (dec1/dec2/dec3), w HWIO from global.
// Thread = 4 couts x RP cols x 2 rows.
// ---------------------------------------------------------------------------
template<int CI, int CO, int RP>
__global__ __launch_bounds__(128,3) void deconvW_kernel(
    const float* __restrict__ in, const float* __restrict__ w,
    const float* __restrict__ bias, float* __restrict__ out,
    int N, int Hin, int Win, int Hout, int Wout)
{
    constexpr int NC  = 4;
    constexpr int CQ  = CO / NC;
    constexpr int G   = 128 / CQ;
    constexpr int RPH = RP / 2;

    const int cq = threadIdx.x % CQ;
    const int g  = threadIdx.x / CQ;
    const int w0 = (blockIdx.x * G + g) * RP;
    const int h0 = blockIdx.y * 2;
    const int n  = blockIdx.z;

    const int  iwb  = w0 >> 1;
    const bool left = (iwb >= 1);
    const int  ihyA = (h0 >> 1) - 1;
    const int  ihyB = (h0 >> 1);

    u64 accE[RP][2], accO[RP][2];
    #pragma unroll
    for (int r=0;r<RP;r++){
        accE[r][0]=0ull; accE[r][1]=0ull;
        accO[r][0]=0ull; accO[r][1]=0ull;
    }

    const float* __restrict__ wp = w + 4*cq;

    auto apply_ky = [&](u64 (&acc)[RP][2], int ky, int ci, const u64 (*px)[4]){
        #pragma unroll
        for (int c=0;c<4;c++){
            ulonglong2 wv0 = *reinterpret_cast<const ulonglong2*>(wp + (size_t)((ky*3+0)*CI + ci + c)*CO);
            ulonglong2 wv1 = *reinterpret_cast<const ulonglong2*>(wp + (size_t)((ky*3+1)*CI + ci + c)*CO);
            ulonglong2 wv2 = *reinterpret_cast<const ulonglong2*>(wp + (size_t)((ky*3+2)*CI + ci + c)*CO);
            #pragma unroll
            for (int t=0;t<RPH;t++){
                ffma2(acc[2*t][0], wv0.x, px[t][c]);
                ffma2(acc[2*t][1], wv0.y, px[t][c]);
            }
            #pragma unroll
            for (int t=1;t<=RPH;t++){
                ffma2(acc[2*t-2][0], wv2.x, px[t][c]);
                ffma2(acc[2*t-2][1], wv2.y, px[t][c]);
                ffma2(acc[2*t-1][0], wv1.x, px[t][c]);
                ffma2(acc[2*t-1][1], wv1.y, px[t][c]);
            }
        }
    };

    #pragma unroll 1
    for (int ci=0; ci<CI; ci+=4){
        u64 px[RPH+1][4];

        if (ihyA >= 0){
            const float* rowp = in + ((size_t)(n*Hin + ihyA)*Win)*CI;
            #pragma unroll
            for (int t=0;t<=RPH;t++){
                if (t==0 && !left){ px[0][0]=px[0][1]=px[0][2]=px[0][3]=0ull; }
                else {
                    float4 xv = *reinterpret_cast<const float4*>(rowp + (size_t)(iwb-1+t)*CI + ci);
                    px[t][0]=pack2(xv.x); px[t][1]=pack2(xv.y);
                    px[t][2]=pack2(xv.z); px[t][3]=pack2(xv.w);
                }
            }
            apply_ky(accE, 0, ci, px);
        }
        {
            const float* rowp = in + ((size_t)(n*Hin + ihyB)*Win)*CI;
            #pragma unroll
            for (int t=0;t<=RPH;t++){
                if (t==0 && !left){ px[0][0]=px[0][1]=px[0][2]=px[0][3]=0ull; }
                else {
                    float4 xv = *reinterpret_cast<const float4*>(rowp + (size_t)(iwb-1+t)*CI + ci);
                    px[t][0]=pack2(xv.x); px[t][1]=pack2(xv.y);
                    px[t][2]=pack2(xv.z); px[t][3]=pack2(xv.w);
                }
            }
            apply_ky(accE, 2, ci, px);
            apply_ky(accO, 1, ci, px);
        }
    }

    const float4 bv = *reinterpret_cast<const float4*>(bias + 4*cq);
    #pragma unroll
    for (int row=0; row<2; row++){
        const size_t ob = ((size_t)(n*Hout + h0 + row)*Wout + w0)*CO + 4*cq;
        #pragma unroll
        for (int r=0;r<RP;r++){
            u64 a0u = row ? accO[r][0] : accE[r][0];
            u64 a1u = row ? accO[r][1] : accE[r][1];
            float a0,a1,a2,a3;
            unpack2(a0,a1,a0u); unpack2(a2,a3,a1u);
            a0 += bv.x; a1 += bv.y; a2 += bv.z; a3 += bv.w;
            a0 = (a0 > 0.f) ? a0 : LRELU_ALPHA * a0;
            a1 = (a1 > 0.f) ? a1 : LRELU_ALPHA * a1;
            a2 = (a2 > 0.f) ? a2 : LRELU_ALPHA * a2;
            a3 = (a3 > 0.f) ? a3 : LRELU_ALPHA * a3;
            float4 o; o.x=a0; o.y=a1; o.z=a2; o.w=a3;
            *reinterpret_cast<float4*>(out + ob + (size_t)r*CO) = o;
        }
    }
}

// ---------------------------------------------------------------------------
// enc1 (CI=3): 256-thr scalar-x conv, 4 couts x RP cols (R9 config)
// ---------------------------------------------------------------------------
template<int CI, int CO, int RP>
__global__ __launch_bounds__(256) void convE_kernel(
    const float* __restrict__ in, const float* __restrict__ w,
    const float* __restrict__ bias, float* __restrict__ out,
    int N, int Hin, int Win, int Hout, int Wout)
{
    constexpr int CQ = CO / 4;
    constexpr int G  = 256 / CQ;

    const int cq = threadIdx.x % CQ;
    const int g  = threadIdx.x / CQ;
    const int w0 = (blockIdx.x * G + g) * RP;
    const int h  = blockIdx.y;
    const int n  = blockIdx.z;
    if (w0 >= Wout) return;

    u64 acc0[RP], acc1[RP];
    #pragma unroll
    for (int r=0;r<RP;r++){ acc0[r]=0ull; acc1[r]=0ull; }

    #pragma unroll
    for (int ky=0; ky<3; ky++){
        int ihy = h*2 + ky;
        if (ihy >= Hin) continue;
        const float* __restrict__ rowp = in + (size_t)(n*Hin + ihy) * Win * CI;
        #pragma unroll
        for (int kx=0; kx<3; kx++){
            const float* __restrict__ wp = w + (size_t)((ky*3+kx)*CI) * CO + 4*cq;
            #pragma unroll
            for (int ci=0; ci<CI; ci++){
                ulonglong2 wv = *reinterpret_cast<const ulonglong2*>(wp + (size_t)ci*CO);
                #pragma unroll
                for (int r=0;r<RP;r++){
                    int iw = (w0+r)*2 + kx;
                    if (iw < Win){
                        u64 p = pack2(rowp[(size_t)iw*CI + ci]);
                        ffma2(acc0[r], wv.x, p);
                        ffma2(acc1[r], wv.y, p);
                    }
                }
            }
        }
    }

    const float4 bv = *reinterpret_cast<const float4*>(bias + 4*cq);
    const size_t ob = ((size_t)(n*Hout + h)*Wout + w0)*CO + 4*cq;
    #pragma unroll
    for (int r=0;r<RP;r++){
        float a0,a1,a2,a3;
        unpack2(a0,a1,acc0[r]); unpack2(a2,a3,acc1[r]);
        a0 += bv.x; a1 += bv.y; a2 += bv.z; a3 += bv.w;
        a0 = (a0 > 0.f) ? a0 : LRELU_ALPHA * a0;
        a1 = (a1 > 0.f) ? a1 : LRELU_ALPHA * a1;
        a2 = (a2 > 0.f) ? a2 : LRELU_ALPHA * a2;
        a3 = (a3 > 0.f) ? a3 : LRELU_ALPHA * a3;
        float4 o; o.x=a0; o.y=a1; o.z=a2; o.w=a3;
        *reinterpret_cast<float4*>(out + ob + (size_t)r*CO) = o;
    }
}

// ---------------------------------------------------------------------------
// fused enc4 (1x1 conv, 64->32) + VQ with precomputed half-norms
// ---------------------------------------------------------------------------
__global__ __launch_bounds__(64) void enc4_vq_kernel(
    const float* __restrict__ h3, const float* __restrict__ w,
    const float* __restrict__ b, const float* __restrict__ cb,
    float* __restrict__ q, int NP)
{
    __shared__ float sw[2048];    // w  [64][32]
    __shared__ float scb[2048];   // cb [32][64]
    __shared__ float shalf[64];   // 0.5*||e_k||^2
    for (int i = threadIdx.x; i < 2048; i += 64){ sw[i] = w[i]; scb[i] = cb[i]; }
    __syncthreads();
    {
        int k = threadIdx.x;
        float s = 0.f;
        #pragma unroll
        for (int d=0;d<32;d++){ float e = scb[d*64 + k]; s += e*e; }
        shalf[k] = 0.5f * s;
    }
    __syncthreads();

    int p = blockIdx.x*blockDim.x + threadIdx.x;
    if (p >= NP) return;
    float z[32];
    #pragma unroll
    for (int d=0;d<32;d++) z[d] = b[d];
    const float* hp = h3 + (size_t)p*64;
    #pragma unroll
    for (int c4=0;c4<64;c4+=4){
        float4 hv = *reinterpret_cast<const float4*>(hp + c4);
        #pragma unroll
        for (int d=0;d<32;d++){
            z[d] += hv.x * sw[(c4+0)*32 + d];
            z[d] += hv.y * sw[(c4+1)*32 + d];
            z[d] += hv.z * sw[(c4+2)*32 + d];
            z[d] += hv.w * sw[(c4+3)*32 + d];
        }
    }
    float best = 3.4e38f; int bk = 0;
    for (int k=0;k<64;k++){
        float dot = 0.f;
        #pragma unroll
        for (int d=0;d<32;d++) dot += z[d] * scb[d*64 + k];
        float score = shalf[k] - dot;
        if (score < best){ best = score; bk = k; }  // strict < == first-min
    }
    float* qp = q + (size_t)p*32;
    #pragma unroll
    for (int d=0;d<32;d++) qp[d] = scb[d*64 + bk];
}

// ---------------------------------------------------------------------------
// dec4: conv_transpose stride 1 (== SAME conv pad 1), CI=32, CO=1.
// ---------------------------------------------------------------------------
__global__ __launch_bounds__(256) void dec4_kernel(
    const float* __restrict__ in, const float* __restrict__ w,
    const float* __restrict__ b, float* __restrict__ out,
    int N, int H, int W)
{
    int gw = (blockIdx.x * blockDim.x + threadIdx.x) >> 5;
    int lane = threadIdx.x & 31;
    int gpr = W >> 2;
    int total = N*H*gpr;
    if (gw >= total) return;
    int gx = gw % gpr; int t = gw / gpr;
    int h = t % H; int n = t / H;
    int w0 = gx*4;

    float wk[9];
    #pragma unroll
    for (int i=0;i<9;i++) wk[i] = w[i*32 + lane];

    float acc[4] = {0.f,0.f,0.f,0.f};
    #pragma unroll
    for (int ky=0;ky<3;ky++){
        int ih = h + ky - 1;
        if (ih < 0 || ih >= H) continue;
        const float* rowp = in + ((size_t)(n*H + ih)*W)*32 + lane;
        float v[6];
        #pragma unroll
        for (int c=0;c<6;c++){
            int iw = w0 - 1 + c;
            v[c] = (iw >= 0 && iw < W) ? rowp[(size_t)iw*32] : 0.f;
        }
        #pragma unroll
        for (int kx=0;kx<3;kx++)
            #pragma unroll
            for (int r=0;r<4;r++)
                acc[r] += v[r+kx] * wk[ky*3+kx];
    }
    float bv = b[0];
    #pragma unroll
    for (int r=0;r<4;r++){
        float a = acc[r];
        #pragma unroll
        for (int o=16;o;o>>=1) a += __shfl_xor_sync(0xffffffffu, a, o);
        if (lane == 0) out[((size_t)(n*H + h)*W) + w0 + r] = a + bv;
    }
}

extern "C" void kernel_launch(void* const* d_in, const int* in_sizes, int n_in,
                              void* d_out, int out_size)
{
    (void)in_sizes; (void)n_in; (void)out_size;
    const float* x   = (const float*)d_in[0];
    const float* e1w = (const float*)d_in[1];  const float* e1b = (const float*)d_in[2];
    const float* e2w = (const float*)d_in[3];  const float* e2b = (const float*)d_in[4];
    const float* e3w = (const float*)d_in[5];  const float* e3b = (const float*)d_in[6];
    const float* e4w = (const float*)d_in[7];  const float* e4b = (const float*)d_in[8];
    const float* cb  = (const float*)d_in[9];
    const float* d1w = (const float*)d_in[10]; const float* d1b = (const float*)d_in[11];
    const float* d2w = (const float*)d_in[12]; const float* d2b = (const float*)d_in[13];
    const float* d3w = (const float*)d_in[14]; const float* d3b = (const float*)d_in[15];
    const float* d4w = (const float*)d_in[16]; const float* d4b = (const float*)d_in[17];
    float* out = (float*)d_out;

    float *A, *B, *WT;
    cudaGetSymbolAddress((void**)&A,  g_bufA);
    cudaGetSymbolAddress((void**)&B,  g_bufB);
    cudaGetSymbolAddress((void**)&WT, g_wT);

    // weight transpose for enc2/enc3 (2 segments)
    transposeP_kernel<<< dim3(144,2), 256 >>>(e2w, e3w, WT);

    // encoder: 256 -> 128 -> 64 -> 32
    convE_kernel<3,32,4><<< dim3(1,128,32), 256 >>>(x, e1w, e1b, A, 32,256,256,128,128);
    // enc2: convP2 CQ=32, G=4 -> 32 cols @ RP=8; Wout=64 -> grid.x=2
    convP2_kernel<32,64,8><<< dim3(2,64,32), 128 >>>(A, WT+0,     e2b, B, 32,128,128, 64, 64);
    // enc3: convP2 CQ=32, G=4 -> 32 cols = Wout @ RP=8
    convP2_kernel<64,64,8><<< dim3(1,32,32), 128 >>>(B, WT+18432, e3b, A, 32, 64, 64, 32, 32);

    // enc4 (1x1) + VQ fused
    enc4_vq_kernel<<< 512, 64 >>>(A, e4w, e4b, cb, B, 32768);

    // decoder: 32 -> 64 -> 128 -> 256 (R9 deconvW throughout)
    deconvW_kernel<32,64,8><<< dim3(1, 32,32), 128 >>>(B, d1w, d1b, A, 32, 32, 32, 64, 64);
    deconvW_kernel<64,64,8><<< dim3(2, 64,32), 128 >>>(A, d2w, d2b, B, 32, 64, 64,128,128);
    deconvW_kernel<64,32,8><<< dim3(2,128,32), 128 >>>(B, d3w, d3b, A, 32,128,128,256,256);

    // dec4: stride-1 deconv == SAME conv, CO=1
    dec4_kernel<<< 65536, 256 >>>(A, d4w, d4b, out, 32, 256, 256);
}

// round 15
// speedup vs baseline: 1.0594x; 1.0594x over previous
#include <cuda_runtime.h>
#include <cstdint>

#define LRELU_ALPHA 0.2f

typedef unsigned long long u64;

// packed f32x2 helpers (sm_103a FFMA2 is PTX-only)
__device__ __forceinline__ void ffma2(u64 &d, u64 a, u64 b){
    asm("fma.rn.f32x2 %0, %1, %2, %0;" : "+l"(d) : "l"(a), "l"(b));
}
__device__ __forceinline__ u64 pack2(float s){
    u64 d; asm("mov.b64 %0, {%1, %1};" : "=l"(d) : "f"(s)); return d;
}
__device__ __forceinline__ void unpack2(float &lo, float &hi, u64 v){
    asm("mov.b64 {%0,%1}, %2;" : "=f"(lo), "=f"(hi) : "l"(v));
}

// ping-pong activation buffers (allocation-free scratch)
__device__ __align__(16) float g_bufA[67108864];   // h1, h3, d1, d3
__device__ __align__(16) float g_bufB[33554432];   // h2, q,  d2

// ---------------------------------------------------------------------------
// R9 wide row-paired deconv (dec1/dec2/dec3), w HWIO from global.
// Thread = 4 couts x RP cols x 2 rows (h0 even, h0+1 odd).
// ---------------------------------------------------------------------------
template<int CI, int CO, int RP>
__global__ __launch_bounds__(128,3) void deconvW_kernel(
    const float* __restrict__ in, const float* __restrict__ w,
    const float* __restrict__ bias, float* __restrict__ out,
    int N, int Hin, int Win, int Hout, int Wout)
{
    constexpr int NC  = 4;
    constexpr int CQ  = CO / NC;
    constexpr int G   = 128 / CQ;
    constexpr int RPH = RP / 2;

    const int cq = threadIdx.x % CQ;
    const int g  = threadIdx.x / CQ;
    const int w0 = (blockIdx.x * G + g) * RP;
    const int h0 = blockIdx.y * 2;
    const int n  = blockIdx.z;

    const int  iwb  = w0 >> 1;
    const bool left = (iwb >= 1);
    const int  ihyA = (h0 >> 1) - 1;
    const int  ihyB = (h0 >> 1);

    u64 accE[RP][2], accO[RP][2];
    #pragma unroll
    for (int r=0;r<RP;r++){
        accE[r][0]=0ull; accE[r][1]=0ull;
        accO[r][0]=0ull; accO[r][1]=0ull;
    }

    const float* __restrict__ wp = w + 4*cq;

    auto apply_ky = [&](u64 (&acc)[RP][2], int ky, int ci, const u64 (*px)[4]){
        #pragma unroll
        for (int c=0;c<4;c++){
            ulonglong2 wv0 = *reinterpret_cast<const ulonglong2*>(wp + (size_t)((ky*3+0)*CI + ci + c)*CO);
            ulonglong2 wv1 = *reinterpret_cast<const ulonglong2*>(wp + (size_t)((ky*3+1)*CI + ci + c)*CO);
            ulonglong2 wv2 = *reinterpret_cast<const ulonglong2*>(wp + (size_t)((ky*3+2)*CI + ci + c)*CO);
            #pragma unroll
            for (int t=0;t<RPH;t++){
                ffma2(acc[2*t][0], wv0.x, px[t][c]);
                ffma2(acc[2*t][1], wv0.y, px[t][c]);
            }
            #pragma unroll
            for (int t=1;t<=RPH;t++){
                ffma2(acc[2*t-2][0], wv2.x, px[t][c]);
                ffma2(acc[2*t-2][1], wv2.y, px[t][c]);
                ffma2(acc[2*t-1][0], wv1.x, px[t][c]);
                ffma2(acc[2*t-1][1], wv1.y, px[t][c]);
            }
        }
    };

    #pragma unroll 1
    for (int ci=0; ci<CI; ci+=4){
        u64 px[RPH+1][4];

        if (ihyA >= 0){
            const float* rowp = in + ((size_t)(n*Hin + ihyA)*Win)*CI;
            #pragma unroll
            for (int t=0;t<=RPH;t++){
                if (t==0 && !left){ px[0][0]=px[0][1]=px[0][2]=px[0][3]=0ull; }
                else {
                    float4 xv = *reinterpret_cast<const float4*>(rowp + (size_t)(iwb-1+t)*CI + ci);
                    px[t][0]=pack2(xv.x); px[t][1]=pack2(xv.y);
                    px[t][2]=pack2(xv.z); px[t][3]=pack2(xv.w);
                }
            }
            apply_ky(accE, 0, ci, px);
        }
        {
            const float* rowp = in + ((size_t)(n*Hin + ihyB)*Win)*CI;
            #pragma unroll
            for (int t=0;t<=RPH;t++){
                if (t==0 && !left){ px[0][0]=px[0][1]=px[0][2]=px[0][3]=0ull; }
                else {
                    float4 xv = *reinterpret_cast<const float4*>(rowp + (size_t)(iwb-1+t)*CI + ci);
                    px[t][0]=pack2(xv.x); px[t][1]=pack2(xv.y);
                    px[t][2]=pack2(xv.z); px[t][3]=pack2(xv.w);
                }
            }
            apply_ky(accE, 2, ci, px);
            apply_ky(accO, 1, ci, px);
        }
    }

    const float4 bv = *reinterpret_cast<const float4*>(bias + 4*cq);
    #pragma unroll
    for (int row=0; row<2; row++){
        const size_t ob = ((size_t)(n*Hout + h0 + row)*Wout + w0)*CO + 4*cq;
        #pragma unroll
        for (int r=0;r<RP;r++){
            u64 a0u = row ? accO[r][0] : accE[r][0];
            u64 a1u = row ? accO[r][1] : accE[r][1];
            float a0,a1,a2,a3;
            unpack2(a0,a1,a0u); unpack2(a2,a3,a1u);
            a0 += bv.x; a1 += bv.y; a2 += bv.z; a3 += bv.w;
            a0 = (a0 > 0.f) ? a0 : LRELU_ALPHA * a0;
            a1 = (a1 > 0.f) ? a1 : LRELU_ALPHA * a1;
            a2 = (a2 > 0.f) ? a2 : LRELU_ALPHA * a2;
            a3 = (a3 > 0.f) ? a3 : LRELU_ALPHA * a3;
            float4 o; o.x=a0; o.y=a1; o.z=a2; o.w=a3;
            *reinterpret_cast<float4*>(out + ob + (size_t)r*CO) = o;
        }
    }
}

// ---------------------------------------------------------------------------
// R9 encoder conv: stride-2 SAME conv (pad_lo=0), 4 couts x RP cols.
// NT = block size, NB = min blocks/SM (occupancy knob).
// ---------------------------------------------------------------------------
template<int CI, int CO, int RP, int NT, int NB>
__global__ __launch_bounds__(NT, NB) void convE_kernel(
    const float* __restrict__ in, const float* __restrict__ w,
    const float* __restrict__ bias, float* __restrict__ out,
    int N, int Hin, int Win, int Hout, int Wout)
{
    constexpr int CQ = CO / 4;
    constexpr int G  = NT / CQ;
    static_assert(RP % 2 == 0, "RP even");

    const int cq = threadIdx.x % CQ;
    const int g  = threadIdx.x / CQ;
    const int w0 = (blockIdx.x * G + g) * RP;
    const int h  = blockIdx.y;
    const int n  = blockIdx.z;
    if (w0 >= Wout) return;

    u64 acc0[RP], acc1[RP];
    #pragma unroll
    for (int r=0;r<RP;r++){ acc0[r]=0ull; acc1[r]=0ull; }

    #pragma unroll
    for (int ky=0; ky<3; ky++){
        int ihy = h*2 + ky;
        if (ihy >= Hin) continue;
        const float* __restrict__ rowp = in + (size_t)(n*Hin + ihy) * Win * CI;

        #pragma unroll
        for (int kx=0; kx<3; kx++){
            const float* __restrict__ wp = w + (size_t)((ky*3+kx)*CI) * CO + 4*cq;
            int  ofs[RP];
            bool v[RP];
            #pragma unroll
            for (int r=0;r<RP;r++){
                int iw = (w0+r)*2 + kx;
                v[r]   = (iw < Win);
                ofs[r] = v[r] ? iw*CI : 0;
            }

            if constexpr (CI % 4 == 0) {
                #pragma unroll 2
                for (int ci=0; ci<CI; ci+=4){
                    ulonglong2 wv0 = *reinterpret_cast<const ulonglong2*>(wp + (size_t)(ci+0)*CO);
                    ulonglong2 wv1 = *reinterpret_cast<const ulonglong2*>(wp + (size_t)(ci+1)*CO);
                    ulonglong2 wv2 = *reinterpret_cast<const ulonglong2*>(wp + (size_t)(ci+2)*CO);
                    ulonglong2 wv3 = *reinterpret_cast<const ulonglong2*>(wp + (size_t)(ci+3)*CO);
                    #pragma unroll
                    for (int r=0;r<RP;r++){
                        if (v[r]){
                            float4 xv = *reinterpret_cast<const float4*>(rowp + ofs[r] + ci);
                            u64 p0 = pack2(xv.x), p1 = pack2(xv.y);
                            u64 p2 = pack2(xv.z), p3 = pack2(xv.w);
                            ffma2(acc0[r], wv0.x, p0); ffma2(acc1[r], wv0.y, p0);
                            ffma2(acc0[r], wv1.x, p1); ffma2(acc1[r], wv1.y, p1);
                            ffma2(acc0[r], wv2.x, p2); ffma2(acc1[r], wv2.y, p2);
                            ffma2(acc0[r], wv3.x, p3); ffma2(acc1[r], wv3.y, p3);
                        }
                    }
                }
            } else {
                #pragma unroll
                for (int ci=0; ci<CI; ci++){
                    ulonglong2 wv = *reinterpret_cast<const ulonglong2*>(wp + (size_t)ci*CO);
                    #pragma unroll
                    for (int r=0;r<RP;r++){
                        if (v[r]){
                            u64 p = pack2(rowp[ofs[r] + ci]);
                            ffma2(acc0[r], wv.x, p);
                            ffma2(acc1[r], wv.y, p);
                        }
                    }
                }
            }
        }
    }

    const float4 bv = *reinterpret_cast<const float4*>(bias + 4*cq);
    const size_t ob = ((size_t)(n*Hout + h)*Wout + w0)*CO + 4*cq;
    #pragma unroll
    for (int r=0;r<RP;r++){
        float a0,a1,a2,a3;
        unpack2(a0,a1,acc0[r]); unpack2(a2,a3,acc1[r]);
        a0 += bv.x; a1 += bv.y; a2 += bv.z; a3 += bv.w;
        a0 = (a0 > 0.f) ? a0 : LRELU_ALPHA * a0;
        a1 = (a1 > 0.f) ? a1 : LRELU_ALPHA * a1;
        a2 = (a2 > 0.f) ? a2 : LRELU_ALPHA * a2;
        a3 = (a3 > 0.f) ? a3 : LRELU_ALPHA * a3;
        float4 o; o.x=a0; o.y=a1; o.z=a2; o.w=a3;
        *reinterpret_cast<float4*>(out + ob + (size_t)r*CO) = o;
    }
}

// ---------------------------------------------------------------------------
// fused enc4 (1x1 conv, 64->32) + VQ with precomputed half-norms
// (EXACT R9 numerics — the VQ argmin is tie-fragile; do not reassociate)
// ---------------------------------------------------------------------------
__global__ __launch_bounds__(64) void enc4_vq_kernel(
    const float* __restrict__ h3, const float* __restrict__ w,
    const float* __restrict__ b, const float* __restrict__ cb,
    float* __restrict__ q, int NP)
{
    __shared__ float sw[2048];    // w  [64][32]
    __shared__ float scb[2048];   // cb [32][64]
    __shared__ float shalf[64];   // 0.5*||e_k||^2
    for (int i = threadIdx.x; i < 2048; i += 64){ sw[i] = w[i]; scb[i] = cb[i]; }
    __syncthreads();
    {
        int k = threadIdx.x;
        float s = 0.f;
        #pragma unroll
        for (int d=0;d<32;d++){ float e = scb[d*64 + k]; s += e*e; }
        shalf[k] = 0.5f * s;
    }
    __syncthreads();

    int p = blockIdx.x*blockDim.x + threadIdx.x;
    if (p >= NP) return;
    float z[32];
    #pragma unroll
    for (int d=0;d<32;d++) z[d] = b[d];
    const float* hp = h3 + (size_t)p*64;
    #pragma unroll
    for (int c4=0;c4<64;c4+=4){
        float4 hv = *reinterpret_cast<const float4*>(hp + c4);
        #pragma unroll
        for (int d=0;d<32;d++){
            z[d] += hv.x * sw[(c4+0)*32 + d];
            z[d] += hv.y * sw[(c4+1)*32 + d];
            z[d] += hv.z * sw[(c4+2)*32 + d];
            z[d] += hv.w * sw[(c4+3)*32 + d];
        }
    }
    float best = 3.4e38f; int bk = 0;
    for (int k=0;k<64;k++){
        float dot = 0.f;
        #pragma unroll
        for (int d=0;d<32;d++) dot += z[d] * scb[d*64 + k];
        float score = shalf[k] - dot;
        if (score < best){ best = score; bk = k; }  // strict < == first-min
    }
    float* qp = q + (size_t)p*32;
    #pragma unroll
    for (int d=0;d<32;d++) qp[d] = scb[d*64 + bk];
}

// ---------------------------------------------------------------------------
// dec4: conv_transpose stride 1 (== SAME conv pad 1), CI=32, CO=1.
// ---------------------------------------------------------------------------
__global__ __launch_bounds__(256) void dec4_kernel(
    const float* __restrict__ in, const float* __restrict__ w,
    const float* __restrict__ b, float* __restrict__ out,
    int N, int H, int W)
{
    int gw = (blockIdx.x * blockDim.x + threadIdx.x) >> 5;
    int lane = threadIdx.x & 31;
    int gpr = W >> 2;
    int total = N*H*gpr;
    if (gw >= total) return;
    int gx = gw % gpr; int t = gw / gpr;
    int h = t % H; int n = t / H;
    int w0 = gx*4;

    float wk[9];
    #pragma unroll
    for (int i=0;i<9;i++) wk[i] = w[i*32 + lane];

    float acc[4] = {0.f,0.f,0.f,0.f};
    #pragma unroll
    for (int ky=0;ky<3;ky++){
        int ih = h + ky - 1;
        if (ih < 0 || ih >= H) continue;
        const float* rowp = in + ((size_t)(n*H + ih)*W)*32 + lane;
        float v[6];
        #pragma unroll
        for (int c=0;c<6;c++){
            int iw = w0 - 1 + c;
            v[c] = (iw >= 0 && iw < W) ? rowp[(size_t)iw*32] : 0.f;
        }
        #pragma unroll
        for (int kx=0;kx<3;kx++)
            #pragma unroll
            for (int r=0;r<4;r++)
                acc[r] += v[r+kx] * wk[ky*3+kx];
    }
    float bv = b[0];
    #pragma unroll
    for (int r=0;r<4;r++){
        float a = acc[r];
        #pragma unroll
        for (int o=16;o;o>>=1) a += __shfl_xor_sync(0xffffffffu, a, o);
        if (lane == 0) out[((size_t)(n*H + h)*W) + w0 + r] = a + bv;
    }
}

extern "C" void kernel_launch(void* const* d_in, const int* in_sizes, int n_in,
                              void* d_out, int out_size)
{
    (void)in_sizes; (void)n_in; (void)out_size;
    const float* x   = (const float*)d_in[0];
    const float* e1w = (const float*)d_in[1];  const float* e1b = (const float*)d_in[2];
    const float* e2w = (const float*)d_in[3];  const float* e2b = (const float*)d_in[4];
    const float* e3w = (const float*)d_in[5];  const float* e3b = (const float*)d_in[6];
    const float* e4w = (const float*)d_in[7];  const float* e4b = (const float*)d_in[8];
    const float* cb  = (const float*)d_in[9];
    const float* d1w = (const float*)d_in[10]; const float* d1b = (const float*)d_in[11];
    const float* d2w = (const float*)d_in[12]; const float* d2b = (const float*)d_in[13];
    const float* d3w = (const float*)d_in[14]; const float* d3b = (const float*)d_in[15];
    const float* d4w = (const float*)d_in[16]; const float* d4b = (const float*)d_in[17];
    float* out = (float*)d_out;

    float *A, *B;
    cudaGetSymbolAddress((void**)&A, g_bufA);
    cudaGetSymbolAddress((void**)&B, g_bufB);

    // encoder: 256 -> 128 -> 64 -> 32  (R9 configs; enc3 NB=4 is the only delta)
    convE_kernel<3,32,4,256,1><<< dim3(1,128,32), 256 >>>(x, e1w, e1b, A, 32,256,256,128,128);
    convE_kernel<32,64,8,128,3><<< dim3(1,64,32), 128 >>>(A, e2w, e2b, B, 32,128,128, 64, 64);
    convE_kernel<64,64,4,128,4><<< dim3(1,32,32), 128 >>>(B, e3w, e3b, A, 32, 64, 64, 32, 32);

    // enc4 (1x1) + VQ fused (R9 scalar numerics)
    enc4_vq_kernel<<< 512, 64 >>>(A, e4w, e4b, cb, B, 32768);

    // decoder: 32 -> 64 -> 128 -> 256 (R9 deconvW)
    deconvW_kernel<32,64,8><<< dim3(1, 32,32), 128 >>>(B, d1w, d1b, A, 32, 32, 32, 64, 64);
    deconvW_kernel<64,64,8><<< dim3(2, 64,32), 128 >>>(A, d2w, d2b, B, 32, 64, 64,128,128);
    deconvW_kernel<64,32,8><<< dim3(2,128,32), 128 >>>(B, d3w, d3b, A, 32,128,128,256,256);

    // dec4: stride-1 deconv == SAME conv, CO=1
    dec4_kernel<<< 65536, 256 >>>(A, d4w, d4b, out, 32, 256, 256);
}

// round 16
// speedup vs baseline: 1.0735x; 1.0133x over previous
#include <cuda_runtime.h>
#include <cstdint>

#define LRELU_ALPHA 0.2f

typedef unsigned long long u64;

// packed f32x2 helpers (sm_103a FFMA2 is PTX-only)
__device__ __forceinline__ void ffma2(u64 &d, u64 a, u64 b){
    asm("fma.rn.f32x2 %0, %1, %2, %0;" : "+l"(d) : "l"(a), "l"(b));
}
__device__ __forceinline__ u64 pack2(float s){
    u64 d; asm("mov.b64 %0, {%1, %1};" : "=l"(d) : "f"(s)); return d;
}
__device__ __forceinline__ void unpack2(float &lo, float &hi, u64 v){
    asm("mov.b64 {%0,%1}, %2;" : "=f"(lo), "=f"(hi) : "l"(v));
}

// ping-pong activation buffers (allocation-free scratch)
__device__ __align__(16) float g_bufA[67108864];   // h1, h3, d1, d3
__device__ __align__(16) float g_bufB[33554432];   // h2, q,  d2

// ---------------------------------------------------------------------------
// Wide row-paired deconv (dec1/dec2/dec3), w HWIO from global.
// Thread = 4 couts x RP cols x 2 rows (h0 even, h0+1 odd).
// UNR = ci-chunk unroll factor: 2 lets ptxas software-pipeline the next
// chunk's x loads under the current chunk's FFMA2s (latency hiding).
// ---------------------------------------------------------------------------
template<int CI, int CO, int RP, int UNR>
__global__ __launch_bounds__(128,3) void deconvW_kernel(
    const float* __restrict__ in, const float* __restrict__ w,
    const float* __restrict__ bias, float* __restrict__ out,
    int N, int Hin, int Win, int Hout, int Wout)
{
    constexpr int NC  = 4;
    constexpr int CQ  = CO / NC;
    constexpr int G   = 128 / CQ;
    constexpr int RPH = RP / 2;

    const int cq = threadIdx.x % CQ;
    const int g  = threadIdx.x / CQ;
    const int w0 = (blockIdx.x * G + g) * RP;
    const int h0 = blockIdx.y * 2;
    const int n  = blockIdx.z;

    const int  iwb  = w0 >> 1;
    const bool left = (iwb >= 1);
    const int  ihyA = (h0 >> 1) - 1;
    const int  ihyB = (h0 >> 1);

    u64 accE[RP][2], accO[RP][2];
    #pragma unroll
    for (int r=0;r<RP;r++){
        accE[r][0]=0ull; accE[r][1]=0ull;
        accO[r][0]=0ull; accO[r][1]=0ull;
    }

    const float* __restrict__ wp = w + 4*cq;

    auto apply_ky = [&](u64 (&acc)[RP][2], int ky, int ci, const u64 (*px)[4]){
        #pragma unroll
        for (int c=0;c<4;c++){
            ulonglong2 wv0 = *reinterpret_cast<const ulonglong2*>(wp + (size_t)((ky*3+0)*CI + ci + c)*CO);
            ulonglong2 wv1 = *reinterpret_cast<const ulonglong2*>(wp + (size_t)((ky*3+1)*CI + ci + c)*CO);
            ulonglong2 wv2 = *reinterpret_cast<const ulonglong2*>(wp + (size_t)((ky*3+2)*CI + ci + c)*CO);
            #pragma unroll
            for (int t=0;t<RPH;t++){
                ffma2(acc[2*t][0], wv0.x, px[t][c]);
                ffma2(acc[2*t][1], wv0.y, px[t][c]);
            }
            #pragma unroll
            for (int t=1;t<=RPH;t++){
                ffma2(acc[2*t-2][0], wv2.x, px[t][c]);
                ffma2(acc[2*t-2][1], wv2.y, px[t][c]);
                ffma2(acc[2*t-1][0], wv1.x, px[t][c]);
                ffma2(acc[2*t-1][1], wv1.y, px[t][c]);
            }
        }
    };

    #pragma unroll UNR
    for (int ci=0; ci<CI; ci+=4){
        u64 px[RPH+1][4];

        if (ihyA >= 0){
            const float* rowp = in + ((size_t)(n*Hin + ihyA)*Win)*CI;
            #pragma unroll
            for (int t=0;t<=RPH;t++){
                if (t==0 && !left){ px[0][0]=px[0][1]=px[0][2]=px[0][3]=0ull; }
                else {
                    float4 xv = *reinterpret_cast<const float4*>(rowp + (size_t)(iwb-1+t)*CI + ci);
                    px[t][0]=pack2(xv.x); px[t][1]=pack2(xv.y);
                    px[t][2]=pack2(xv.z); px[t][3]=pack2(xv.w);
                }
            }
            apply_ky(accE, 0, ci, px);
        }
        {
            const float* rowp = in + ((size_t)(n*Hin + ihyB)*Win)*CI;
            #pragma unroll
            for (int t=0;t<=RPH;t++){
                if (t==0 && !left){ px[0][0]=px[0][1]=px[0][2]=px[0][3]=0ull; }
                else {
                    float4 xv = *reinterpret_cast<const float4*>(rowp + (size_t)(iwb-1+t)*CI + ci);
                    px[t][0]=pack2(xv.x); px[t][1]=pack2(xv.y);
                    px[t][2]=pack2(xv.z); px[t][3]=pack2(xv.w);
                }
            }
            apply_ky(accE, 2, ci, px);
            apply_ky(accO, 1, ci, px);
        }
    }

    const float4 bv = *reinterpret_cast<const float4*>(bias + 4*cq);
    #pragma unroll
    for (int row=0; row<2; row++){
        const size_t ob = ((size_t)(n*Hout + h0 + row)*Wout + w0)*CO + 4*cq;
        #pragma unroll
        for (int r=0;r<RP;r++){
            u64 a0u = row ? accO[r][0] : accE[r][0];
            u64 a1u = row ? accO[r][1] : accE[r][1];
            float a0,a1,a2,a3;
            unpack2(a0,a1,a0u); unpack2(a2,a3,a1u);
            a0 += bv.x; a1 += bv.y; a2 += bv.z; a3 += bv.w;
            a0 = (a0 > 0.f) ? a0 : LRELU_ALPHA * a0;
            a1 = (a1 > 0.f) ? a1 : LRELU_ALPHA * a1;
            a2 = (a2 > 0.f) ? a2 : LRELU_ALPHA * a2;
            a3 = (a3 > 0.f) ? a3 : LRELU_ALPHA * a3;
            float4 o; o.x=a0; o.y=a1; o.z=a2; o.w=a3;
            *reinterpret_cast<float4*>(out + ob + (size_t)r*CO) = o;
        }
    }
}

// ---------------------------------------------------------------------------
// R9 encoder conv: stride-2 SAME conv (pad_lo=0), 4 couts x RP cols.
// ---------------------------------------------------------------------------
template<int CI, int CO, int RP, int NT, int NB>
__global__ __launch_bounds__(NT, NB) void convE_kernel(
    const float* __restrict__ in, const float* __restrict__ w,
    const float* __restrict__ bias, float* __restrict__ out,
    int N, int Hin, int Win, int Hout, int Wout)
{
    constexpr int CQ = CO / 4;
    constexpr int G  = NT / CQ;
    static_assert(RP % 2 == 0, "RP even");

    const int cq = threadIdx.x % CQ;
    const int g  = threadIdx.x / CQ;
    const int w0 = (blockIdx.x * G + g) * RP;
    const int h  = blockIdx.y;
    const int n  = blockIdx.z;
    if (w0 >= Wout) return;

    u64 acc0[RP], acc1[RP];
    #pragma unroll
    for (int r=0;r<RP;r++){ acc0[r]=0ull; acc1[r]=0ull; }

    #pragma unroll
    for (int ky=0; ky<3; ky++){
        int ihy = h*2 + ky;
        if (ihy >= Hin) continue;
        const float* __restrict__ rowp = in + (size_t)(n*Hin + ihy) * Win * CI;

        #pragma unroll
        for (int kx=0; kx<3; kx++){
            const float* __restrict__ wp = w + (size_t)((ky*3+kx)*CI) * CO + 4*cq;
            int  ofs[RP];
            bool v[RP];
            #pragma unroll
            for (int r=0;r<RP;r++){
                int iw = (w0+r)*2 + kx;
                v[r]   = (iw < Win);
                ofs[r] = v[r] ? iw*CI : 0;
            }

            if constexpr (CI % 4 == 0) {
                #pragma unroll 2
                for (int ci=0; ci<CI; ci+=4){
                    ulonglong2 wv0 = *reinterpret_cast<const ulonglong2*>(wp + (size_t)(ci+0)*CO);
                    ulonglong2 wv1 = *reinterpret_cast<const ulonglong2*>(wp + (size_t)(ci+1)*CO);
                    ulonglong2 wv2 = *reinterpret_cast<const ulonglong2*>(wp + (size_t)(ci+2)*CO);
                    ulonglong2 wv3 = *reinterpret_cast<const ulonglong2*>(wp + (size_t)(ci+3)*CO);
                    #pragma unroll
                    for (int r=0;r<RP;r++){
                        if (v[r]){
                            float4 xv = *reinterpret_cast<const float4*>(rowp + ofs[r] + ci);
                            u64 p0 = pack2(xv.x), p1 = pack2(xv.y);
                            u64 p2 = pack2(xv.z), p3 = pack2(xv.w);
                            ffma2(acc0[r], wv0.x, p0); ffma2(acc1[r], wv0.y, p0);
                            ffma2(acc0[r], wv1.x, p1); ffma2(acc1[r], wv1.y, p1);
                            ffma2(acc0[r], wv2.x, p2); ffma2(acc1[r], wv2.y, p2);
                            ffma2(acc0[r], wv3.x, p3); ffma2(acc1[r], wv3.y, p3);
                        }
                    }
                }
            } else {
                #pragma unroll
                for (int ci=0; ci<CI; ci++){
                    ulonglong2 wv = *reinterpret_cast<const ulonglong2*>(wp + (size_t)ci*CO);
                    #pragma unroll
                    for (int r=0;r<RP;r++){
                        if (v[r]){
                            u64 p = pack2(rowp[ofs[r] + ci]);
                            ffma2(acc0[r], wv.x, p);
                            ffma2(acc1[r], wv.y, p);
                        }
                    }
                }
            }
        }
    }

    const float4 bv = *reinterpret_cast<const float4*>(bias + 4*cq);
    const size_t ob = ((size_t)(n*Hout + h)*Wout + w0)*CO + 4*cq;
    #pragma unroll
    for (int r=0;r<RP;r++){
        float a0,a1,a2,a3;
        unpack2(a0,a1,acc0[r]); unpack2(a2,a3,acc1[r]);
        a0 += bv.x; a1 += bv.y; a2 += bv.z; a3 += bv.w;
        a0 = (a0 > 0.f) ? a0 : LRELU_ALPHA * a0;
        a1 = (a1 > 0.f) ? a1 : LRELU_ALPHA * a1;
        a2 = (a2 > 0.f) ? a2 : LRELU_ALPHA * a2;
        a3 = (a3 > 0.f) ? a3 : LRELU_ALPHA * a3;
        float4 o; o.x=a0; o.y=a1; o.z=a2; o.w=a3;
        *reinterpret_cast<float4*>(out + ob + (size_t)r*CO) = o;
    }
}

// ---------------------------------------------------------------------------
// fused enc4 (1x1 conv, 64->32) + VQ with precomputed half-norms
// (EXACT R9 numerics — the VQ argmin is tie-fragile; do not reassociate)
// ---------------------------------------------------------------------------
__global__ __launch_bounds__(64) void enc4_vq_kernel(
    const float* __restrict__ h3, const float* __restrict__ w,
    const float* __restrict__ b, const float* __restrict__ cb,
    float* __restrict__ q, int NP)
{
    __shared__ float sw[2048];    // w  [64][32]
    __shared__ float scb[2048];   // cb [32][64]
    __shared__ float shalf[64];   // 0.5*||e_k||^2
    for (int i = threadIdx.x; i < 2048; i += 64){ sw[i] = w[i]; scb[i] = cb[i]; }
    __syncthreads();
    {
        int k = threadIdx.x;
        float s = 0.f;
        #pragma unroll
        for (int d=0;d<32;d++){ float e = scb[d*64 + k]; s += e*e; }
        shalf[k] = 0.5f * s;
    }
    __syncthreads();

    int p = blockIdx.x*blockDim.x + threadIdx.x;
    if (p >= NP) return;
    float z[32];
    #pragma unroll
    for (int d=0;d<32;d++) z[d] = b[d];
    const float* hp = h3 + (size_t)p*64;
    #pragma unroll
    for (int c4=0;c4<64;c4+=4){
        float4 hv = *reinterpret_cast<const float4*>(hp + c4);
        #pragma unroll
        for (int d=0;d<32;d++){
            z[d] += hv.x * sw[(c4+0)*32 + d];
            z[d] += hv.y * sw[(c4+1)*32 + d];
            z[d] += hv.z * sw[(c4+2)*32 + d];
            z[d] += hv.w * sw[(c4+3)*32 + d];
        }
    }
    float best = 3.4e38f; int bk = 0;
    for (int k=0;k<64;k++){
        float dot = 0.f;
        #pragma unroll
        for (int d=0;d<32;d++) dot += z[d] * scb[d*64 + k];
        float score = shalf[k] - dot;
        if (score < best){ best = score; bk = k; }  // strict < == first-min
    }
    float* qp = q + (size_t)p*32;
    #pragma unroll
    for (int d=0;d<32;d++) qp[d] = scb[d*64 + bk];
}

// ---------------------------------------------------------------------------
// dec4: conv_transpose stride 1 (== SAME conv pad 1), CI=32, CO=1.
// warp handles 8 consecutive output columns (v[10] input cols staged).
// ---------------------------------------------------------------------------
__global__ __launch_bounds__(256) void dec4_kernel(
    const float* __restrict__ in, const float* __restrict__ w,
    const float* __restrict__ b, float* __restrict__ out,
    int N, int H, int W)
{
    int gw = (blockIdx.x * blockDim.x + threadIdx.x) >> 5;
    int lane = threadIdx.x & 31;
    int gpr = W >> 3;                 // 8-col groups per row
    int total = N*H*gpr;
    if (gw >= total) return;
    int gx = gw % gpr; int t = gw / gpr;
    int h = t % H; int n = t / H;
    int w0 = gx*8;

    float wk[9];
    #pragma unroll
    for (int i=0;i<9;i++) wk[i] = w[i*32 + lane];

    float acc[8] = {0.f,0.f,0.f,0.f,0.f,0.f,0.f,0.f};
    #pragma unroll
    for (int ky=0;ky<3;ky++){
        int ih = h + ky - 1;
        if (ih < 0 || ih >= H) continue;
        const float* rowp = in + ((size_t)(n*H + ih)*W)*32 + lane;
        float v[10];
        #pragma unroll
        for (int c=0;c<10;c++){
            int iw = w0 - 1 + c;
            v[c] = (iw >= 0 && iw < W) ? rowp[(size_t)iw*32] : 0.f;
        }
        #pragma unroll
        for (int kx=0;kx<3;kx++)
            #pragma unroll
            for (int r=0;r<8;r++)
                acc[r] += v[r+kx] * wk[ky*3+kx];
    }
    float bv = b[0];
    #pragma unroll
    for (int r=0;r<8;r++){
        float a = acc[r];
        #pragma unroll
        for (int o=16;o;o>>=1) a += __shfl_xor_sync(0xffffffffu, a, o);
        if (lane == 0) out[((size_t)(n*H + h)*W) + w0 + r] = a + bv;
    }
}

extern "C" void kernel_launch(void* const* d_in, const int* in_sizes, int n_in,
                              void* d_out, int out_size)
{
    (void)in_sizes; (void)n_in; (void)out_size;
    const float* x   = (const float*)d_in[0];
    const float* e1w = (const float*)d_in[1];  const float* e1b = (const float*)d_in[2];
    const float* e2w = (const float*)d_in[3];  const float* e2b = (const float*)d_in[4];
    const float* e3w = (const float*)d_in[5];  const float* e3b = (const float*)d_in[6];
    const float* e4w = (const float*)d_in[7];  const float* e4b = (const float*)d_in[8];
    const float* cb  = (const float*)d_in[9];
    const float* d1w = (const float*)d_in[10]; const float* d1b = (const float*)d_in[11];
    const float* d2w = (const float*)d_in[12]; const float* d2b = (const float*)d_in[13];
    const float* d3w = (const float*)d_in[14]; const float* d3b = (const float*)d_in[15];
    const float* d4w = (const float*)d_in[16]; const float* d4b = (const float*)d_in[17];
    float* out = (float*)d_out;

    float *A, *B;
    cudaGetSymbolAddress((void**)&A, g_bufA);
    cudaGetSymbolAddress((void**)&B, g_bufB);

    // encoder: 256 -> 128 -> 64 -> 32  (R15 configs)
    convE_kernel<3,32,4,256,1><<< dim3(1,128,32), 256 >>>(x, e1w, e1b, A, 32,256,256,128,128);
    convE_kernel<32,64,8,128,3><<< dim3(1,64,32), 128 >>>(A, e2w, e2b, B, 32,128,128, 64, 64);
    convE_kernel<64,64,4,128,4><<< dim3(1,32,32), 128 >>>(B, e3w, e3b, A, 32, 64, 64, 32, 32);

    // enc4 (1x1) + VQ fused (R9 scalar numerics)
    enc4_vq_kernel<<< 512, 64 >>>(A, e4w, e4b, cb, B, 32768);

    // decoder: 32 -> 64 -> 128 -> 256
    // dec1: unroll 1 (control); dec2/dec3: unroll 2 (software pipelining)
    deconvW_kernel<32,64,8,1><<< dim3(1, 32,32), 128 >>>(B, d1w, d1b, A, 32, 32, 32, 64, 64);
    deconvW_kernel<64,64,8,2><<< dim3(2, 64,32), 128 >>>(A, d2w, d2b, B, 32, 64, 64,128,128);
    deconvW_kernel<64,32,8,2><<< dim3(2,128,32), 128 >>>(B, d3w, d3b, A, 32,128,128,256,256);

    // dec4: stride-1 deconv == SAME conv, CO=1, 8 cols/warp
    dec4_kernel<<< 32768, 256 >>>(A, d4w, d4b, out, 32, 256, 256);
}

// round 17
// speedup vs baseline: 1.0811x; 1.0071x over previous
#include <cuda_runtime.h>
#include <cstdint>

#define LRELU_ALPHA 0.2f

typedef unsigned long long u64;

// packed f32x2 helpers (sm_103a FFMA2 is PTX-only)
__device__ __forceinline__ void ffma2(u64 &d, u64 a, u64 b){
    asm("fma.rn.f32x2 %0, %1, %2, %0;" : "+l"(d) : "l"(a), "l"(b));
}
__device__ __forceinline__ u64 pack2(float s){
    u64 d; asm("mov.b64 %0, {%1, %1};" : "=l"(d) : "f"(s)); return d;
}
__device__ __forceinline__ void unpack2(float &lo, float &hi, u64 v){
    asm("mov.b64 {%0,%1}, %2;" : "=f"(lo), "=f"(hi) : "l"(v));
}

// ping-pong activation buffers (allocation-free scratch)
__device__ __align__(16) float g_bufA[67108864];   // h1, h3, d1, d3
__device__ __align__(16) float g_bufB[33554432];   // h2, q,  d2

// ---------------------------------------------------------------------------
// Wide row-paired deconv (dec1/dec2/dec3), w HWIO from global.
// Thread = 4 couts x RP cols x 2 rows (h0 even, h0+1 odd).
// UNR = ci-chunk unroll (software pipelining knob).
// ---------------------------------------------------------------------------
template<int CI, int CO, int RP, int UNR>
__global__ __launch_bounds__(128,3) void deconvW_kernel(
    const float* __restrict__ in, const float* __restrict__ w,
    const float* __restrict__ bias, float* __restrict__ out,
    int N, int Hin, int Win, int Hout, int Wout)
{
    constexpr int NC  = 4;
    constexpr int CQ  = CO / NC;
    constexpr int G   = 128 / CQ;
    constexpr int RPH = RP / 2;

    const int cq = threadIdx.x % CQ;
    const int g  = threadIdx.x / CQ;
    const int w0 = (blockIdx.x * G + g) * RP;
    const int h0 = blockIdx.y * 2;
    const int n  = blockIdx.z;

    const int  iwb  = w0 >> 1;
    const bool left = (iwb >= 1);
    const int  ihyA = (h0 >> 1) - 1;
    const int  ihyB = (h0 >> 1);

    u64 accE[RP][2], accO[RP][2];
    #pragma unroll
    for (int r=0;r<RP;r++){
        accE[r][0]=0ull; accE[r][1]=0ull;
        accO[r][0]=0ull; accO[r][1]=0ull;
    }

    const float* __restrict__ wp = w + 4*cq;

    auto apply_ky = [&](u64 (&acc)[RP][2], int ky, int ci, const u64 (*px)[4]){
        #pragma unroll
        for (int c=0;c<4;c++){
            ulonglong2 wv0 = *reinterpret_cast<const ulonglong2*>(wp + (size_t)((ky*3+0)*CI + ci + c)*CO);
            ulonglong2 wv1 = *reinterpret_cast<const ulonglong2*>(wp + (size_t)((ky*3+1)*CI + ci + c)*CO);
            ulonglong2 wv2 = *reinterpret_cast<const ulonglong2*>(wp + (size_t)((ky*3+2)*CI + ci + c)*CO);
            #pragma unroll
            for (int t=0;t<RPH;t++){
                ffma2(acc[2*t][0], wv0.x, px[t][c]);
                ffma2(acc[2*t][1], wv0.y, px[t][c]);
            }
            #pragma unroll
            for (int t=1;t<=RPH;t++){
                ffma2(acc[2*t-2][0], wv2.x, px[t][c]);
                ffma2(acc[2*t-2][1], wv2.y, px[t][c]);
                ffma2(acc[2*t-1][0], wv1.x, px[t][c]);
                ffma2(acc[2*t-1][1], wv1.y, px[t][c]);
            }
        }
    };

    #pragma unroll UNR
    for (int ci=0; ci<CI; ci+=4){
        u64 px[RPH+1][4];

        if (ihyA >= 0){
            const float* rowp = in + ((size_t)(n*Hin + ihyA)*Win)*CI;
            #pragma unroll
            for (int t=0;t<=RPH;t++){
                if (t==0 && !left){ px[0][0]=px[0][1]=px[0][2]=px[0][3]=0ull; }
                else {
                    float4 xv = *reinterpret_cast<const float4*>(rowp + (size_t)(iwb-1+t)*CI + ci);
                    px[t][0]=pack2(xv.x); px[t][1]=pack2(xv.y);
                    px[t][2]=pack2(xv.z); px[t][3]=pack2(xv.w);
                }
            }
            apply_ky(accE, 0, ci, px);
        }
        {
            const float* rowp = in + ((size_t)(n*Hin + ihyB)*Win)*CI;
            #pragma unroll
            for (int t=0;t<=RPH;t++){
                if (t==0 && !left){ px[0][0]=px[0][1]=px[0][2]=px[0][3]=0ull; }
                else {
                    float4 xv = *reinterpret_cast<const float4*>(rowp + (size_t)(iwb-1+t)*CI + ci);
                    px[t][0]=pack2(xv.x); px[t][1]=pack2(xv.y);
                    px[t][2]=pack2(xv.z); px[t][3]=pack2(xv.w);
                }
            }
            apply_ky(accE, 2, ci, px);
            apply_ky(accO, 1, ci, px);
        }
    }

    const float4 bv = *reinterpret_cast<const float4*>(bias + 4*cq);
    #pragma unroll
    for (int row=0; row<2; row++){
        const size_t ob = ((size_t)(n*Hout + h0 + row)*Wout + w0)*CO + 4*cq;
        #pragma unroll
        for (int r=0;r<RP;r++){
            u64 a0u = row ? accO[r][0] : accE[r][0];
            u64 a1u = row ? accO[r][1] : accE[r][1];
            float a0,a1,a2,a3;
            unpack2(a0,a1,a0u); unpack2(a2,a3,a1u);
            a0 += bv.x; a1 += bv.y; a2 += bv.z; a3 += bv.w;
            a0 = (a0 > 0.f) ? a0 : LRELU_ALPHA * a0;
            a1 = (a1 > 0.f) ? a1 : LRELU_ALPHA * a1;
            a2 = (a2 > 0.f) ? a2 : LRELU_ALPHA * a2;
            a3 = (a3 > 0.f) ? a3 : LRELU_ALPHA * a3;
            float4 o; o.x=a0; o.y=a1; o.z=a2; o.w=a3;
            *reinterpret_cast<float4*>(out + ob + (size_t)r*CO) = o;
        }
    }
}

// ---------------------------------------------------------------------------
// Encoder conv: stride-2 SAME conv (pad_lo=0), 4 couts x RP cols.
// NT = block size, NB = min blocks/SM, UNR = inner ci-loop unroll.
// ---------------------------------------------------------------------------
template<int CI, int CO, int RP, int NT, int NB, int UNR>
__global__ __launch_bounds__(NT, NB) void convE_kernel(
    const float* __restrict__ in, const float* __restrict__ w,
    const float* __restrict__ bias, float* __restrict__ out,
    int N, int Hin, int Win, int Hout, int Wout)
{
    constexpr int CQ = CO / 4;
    constexpr int G  = NT / CQ;
    static_assert(RP % 2 == 0, "RP even");

    const int cq = threadIdx.x % CQ;
    const int g  = threadIdx.x / CQ;
    const int w0 = (blockIdx.x * G + g) * RP;
    const int h  = blockIdx.y;
    const int n  = blockIdx.z;
    if (w0 >= Wout) return;

    u64 acc0[RP], acc1[RP];
    #pragma unroll
    for (int r=0;r<RP;r++){ acc0[r]=0ull; acc1[r]=0ull; }

    #pragma unroll
    for (int ky=0; ky<3; ky++){
        int ihy = h*2 + ky;
        if (ihy >= Hin) continue;
        const float* __restrict__ rowp = in + (size_t)(n*Hin + ihy) * Win * CI;

        #pragma unroll
        for (int kx=0; kx<3; kx++){
            const float* __restrict__ wp = w + (size_t)((ky*3+kx)*CI) * CO + 4*cq;
            int  ofs[RP];
            bool v[RP];
            #pragma unroll
            for (int r=0;r<RP;r++){
                int iw = (w0+r)*2 + kx;
                v[r]   = (iw < Win);
                ofs[r] = v[r] ? iw*CI : 0;
            }

            if constexpr (CI % 4 == 0) {
                #pragma unroll UNR
                for (int ci=0; ci<CI; ci+=4){
                    ulonglong2 wv0 = *reinterpret_cast<const ulonglong2*>(wp + (size_t)(ci+0)*CO);
                    ulonglong2 wv1 = *reinterpret_cast<const ulonglong2*>(wp + (size_t)(ci+1)*CO);
                    ulonglong2 wv2 = *reinterpret_cast<const ulonglong2*>(wp + (size_t)(ci+2)*CO);
                    ulonglong2 wv3 = *reinterpret_cast<const ulonglong2*>(wp + (size_t)(ci+3)*CO);
                    #pragma unroll
                    for (int r=0;r<RP;r++){
                        if (v[r]){
                            float4 xv = *reinterpret_cast<const float4*>(rowp + ofs[r] + ci);
                            u64 p0 = pack2(xv.x), p1 = pack2(xv.y);
                            u64 p2 = pack2(xv.z), p3 = pack2(xv.w);
                            ffma2(acc0[r], wv0.x, p0); ffma2(acc1[r], wv0.y, p0);
                            ffma2(acc0[r], wv1.x, p1); ffma2(acc1[r], wv1.y, p1);
                            ffma2(acc0[r], wv2.x, p2); ffma2(acc1[r], wv2.y, p2);
                            ffma2(acc0[r], wv3.x, p3); ffma2(acc1[r], wv3.y, p3);
                        }
                    }
                }
            } else {
                #pragma unroll
                for (int ci=0; ci<CI; ci++){
                    ulonglong2 wv = *reinterpret_cast<const ulonglong2*>(wp + (size_t)ci*CO);
                    #pragma unroll
                    for (int r=0;r<RP;r++){
                        if (v[r]){
                            u64 p = pack2(rowp[ofs[r] + ci]);
                            ffma2(acc0[r], wv.x, p);
                            ffma2(acc1[r], wv.y, p);
                        }
                    }
                }
            }
        }
    }

    const float4 bv = *reinterpret_cast<const float4*>(bias + 4*cq);
    const size_t ob = ((size_t)(n*Hout + h)*Wout + w0)*CO + 4*cq;
    #pragma unroll
    for (int r=0;r<RP;r++){
        float a0,a1,a2,a3;
        unpack2(a0,a1,acc0[r]); unpack2(a2,a3,acc1[r]);
        a0 += bv.x; a1 += bv.y; a2 += bv.z; a3 += bv.w;
        a0 = (a0 > 0.f) ? a0 : LRELU_ALPHA * a0;
        a1 = (a1 > 0.f) ? a1 : LRELU_ALPHA * a1;
        a2 = (a2 > 0.f) ? a2 : LRELU_ALPHA * a2;
        a3 = (a3 > 0.f) ? a3 : LRELU_ALPHA * a3;
        float4 o; o.x=a0; o.y=a1; o.z=a2; o.w=a3;
        *reinterpret_cast<float4*>(out + ob + (size_t)r*CO) = o;
    }
}

// ---------------------------------------------------------------------------
// fused enc4 (1x1 conv, 64->32) + VQ with precomputed half-norms
// (EXACT R9 numerics — the VQ argmin is tie-fragile; do not reassociate)
// ---------------------------------------------------------------------------
__global__ __launch_bounds__(64) void enc4_vq_kernel(
    const float* __restrict__ h3, const float* __restrict__ w,
    const float* __restrict__ b, const float* __restrict__ cb,
    float* __restrict__ q, int NP)
{
    __shared__ float sw[2048];    // w  [64][32]
    __shared__ float scb[2048];   // cb [32][64]
    __shared__ float shalf[64];   // 0.5*||e_k||^2
    for (int i = threadIdx.x; i < 2048; i += 64){ sw[i] = w[i]; scb[i] = cb[i]; }
    __syncthreads();
    {
        int k = threadIdx.x;
        float s = 0.f;
        #pragma unroll
        for (int d=0;d<32;d++){ float e = scb[d*64 + k]; s += e*e; }
        shalf[k] = 0.5f * s;
    }
    __syncthreads();

    int p = blockIdx.x*blockDim.x + threadIdx.x;
    if (p >= NP) return;
    float z[32];
    #pragma unroll
    for (int d=0;d<32;d++) z[d] = b[d];
    const float* hp = h3 + (size_t)p*64;
    #pragma unroll
    for (int c4=0;c4<64;c4+=4){
        float4 hv = *reinterpret_cast<const float4*>(hp + c4);
        #pragma unroll
        for (int d=0;d<32;d++){
            z[d] += hv.x * sw[(c4+0)*32 + d];
            z[d] += hv.y * sw[(c4+1)*32 + d];
            z[d] += hv.z * sw[(c4+2)*32 + d];
            z[d] += hv.w * sw[(c4+3)*32 + d];
        }
    }
    float best = 3.4e38f; int bk = 0;
    for (int k=0;k<64;k++){
        float dot = 0.f;
        #pragma unroll
        for (int d=0;d<32;d++) dot += z[d] * scb[d*64 + k];
        float score = shalf[k] - dot;
        if (score < best){ best = score; bk = k; }  // strict < == first-min
    }
    float* qp = q + (size_t)p*32;
    #pragma unroll
    for (int d=0;d<32;d++) qp[d] = scb[d*64 + bk];
}

// ---------------------------------------------------------------------------
// dec4: conv_transpose stride 1 (== SAME conv pad 1), CI=32, CO=1.
// warp handles 8 consecutive output columns (v[10] input cols staged).
// ---------------------------------------------------------------------------
__global__ __launch_bounds__(256) void dec4_kernel(
    const float* __restrict__ in, const float* __restrict__ w,
    const float* __restrict__ b, float* __restrict__ out,
    int N, int H, int W)
{
    int gw = (blockIdx.x * blockDim.x + threadIdx.x) >> 5;
    int lane = threadIdx.x & 31;
    int gpr = W >> 3;
    int total = N*H*gpr;
    if (gw >= total) return;
    int gx = gw % gpr; int t = gw / gpr;
    int h = t % H; int n = t / H;
    int w0 = gx*8;

    float wk[9];
    #pragma unroll
    for (int i=0;i<9;i++) wk[i] = w[i*32 + lane];

    float acc[8] = {0.f,0.f,0.f,0.f,0.f,0.f,0.f,0.f};
    #pragma unroll
    for (int ky=0;ky<3;ky++){
        int ih = h + ky - 1;
        if (ih < 0 || ih >= H) continue;
        const float* rowp = in + ((size_t)(n*H + ih)*W)*32 + lane;
        float v[10];
        #pragma unroll
        for (int c=0;c<10;c++){
            int iw = w0 - 1 + c;
            v[c] = (iw >= 0 && iw < W) ? rowp[(size_t)iw*32] : 0.f;
        }
        #pragma unroll
        for (int kx=0;kx<3;kx++)
            #pragma unroll
            for (int r=0;r<8;r++)
                acc[r] += v[r+kx] * wk[ky*3+kx];
    }
    float bv = b[0];
    #pragma unroll
    for (int r=0;r<8;r++){
        float a = acc[r];
        #pragma unroll
        for (int o=16;o;o>>=1) a += __shfl_xor_sync(0xffffffffu, a, o);
        if (lane == 0) out[((size_t)(n*H + h)*W) + w0 + r] = a + bv;
    }
}

extern "C" void kernel_launch(void* const* d_in, const int* in_sizes, int n_in,
                              void* d_out, int out_size)
{
    (void)in_sizes; (void)n_in; (void)out_size;
    const float* x   = (const float*)d_in[0];
    const float* e1w = (const float*)d_in[1];  const float* e1b = (const float*)d_in[2];
    const float* e2w = (const float*)d_in[3];  const float* e2b = (const float*)d_in[4];
    const float* e3w = (const float*)d_in[5];  const float* e3b = (const float*)d_in[6];
    const float* e4w = (const float*)d_in[7];  const float* e4b = (const float*)d_in[8];
    const float* cb  = (const float*)d_in[9];
    const float* d1w = (const float*)d_in[10]; const float* d1b = (const float*)d_in[11];
    const float* d2w = (const float*)d_in[12]; const float* d2b = (const float*)d_in[13];
    const float* d3w = (const float*)d_in[14]; const float* d3b = (const float*)d_in[15];
    const float* d4w = (const float*)d_in[16]; const float* d4b = (const float*)d_in[17];
    float* out = (float*)d_out;

    float *A, *B;
    cudaGetSymbolAddress((void**)&A, g_bufA);
    cudaGetSymbolAddress((void**)&B, g_bufB);

    // encoder: 256 -> 128 -> 64 -> 32
    convE_kernel<3,32,4,256,1,2><<< dim3(1,128,32), 256 >>>(x, e1w, e1b, A, 32,256,256,128,128);
    convE_kernel<32,64,8,128,3,2><<< dim3(1,64,32), 128 >>>(A, e2w, e2b, B, 32,128,128, 64, 64);
    convE_kernel<64,64,4,128,3,4><<< dim3(1,32,32), 128 >>>(B, e3w, e3b, A, 32, 64, 64, 32, 32);

    // enc4 (1x1) + VQ fused (R9 scalar numerics)
    enc4_vq_kernel<<< 512, 64 >>>(A, e4w, e4b, cb, B, 32768);

    // decoder: 32 -> 64 -> 128 -> 256 (all UNR=2 software pipelining)
    deconvW_kernel<32,64,8,2><<< dim3(1, 32,32), 128 >>>(B, d1w, d1b, A, 32, 32, 32, 64, 64);
    deconvW_kernel<64,64,8,2><<< dim3(2, 64,32), 128 >>>(A, d2w, d2b, B, 32, 64, 64,128,128);
    deconvW_kernel<64,32,8,2><<< dim3(2,128,32), 128 >>>(B, d3w, d3b, A, 32,128,128,256,256);

    // dec4: stride-1 deconv == SAME conv, CO=1, 8 cols/warp
    dec4_kernel<<< 32768, 256 >>>(A, d4w, d4b, out, 32, 256, 256);
}